// round 4
// baseline (speedup 1.0000x reference)
#include <cuda_runtime.h>
#include <math.h>

// ---------------------------------------------------------------------------
// TropicalMLP: with temp=1, trop_linear(x;W,b) = log(exp(x) @ exp(W)^T) + b.
// fused exp -> GEMM+log -> sortLN+relu+exp -> GEMM+log -> sortLN+relu+exp
// -> GEMM+log.  GEMMs in fp32 FFMA (LN's tiny IQR amplifies rounding ~100x).
// R3 change: 256-thread GEMM CTAs (2 warps/SMSP instead of 1) to hide
// LDS/barrier latency; dedicated 64x32 shape for layer 3 (128 CTAs).
// ---------------------------------------------------------------------------

#define KDIM 512

__device__ float g_Ew1[512 * 512];
__device__ float g_Ew2[512 * 512];
__device__ float g_Ew3[256 * 512];
__device__ float g_bufA[1024 * 512];
__device__ float g_bufB[1024 * 512];
__device__ float g_H[1024 * 512];

// ---------------------------------------------------------------------------
__global__ __launch_bounds__(256) void exp_all_kernel(
    const float* __restrict__ x,  float* __restrict__ ex,
    const float* __restrict__ w1, float* __restrict__ e1,
    const float* __restrict__ w2, float* __restrict__ e2,
    const float* __restrict__ w3, float* __restrict__ e3) {
    int i = blockIdx.x * 256 + threadIdx.x;  // float4 index
    const float* s; float* d; int off;
    if (i < 131072)      { s = x;  d = ex; off = i; }
    else if (i < 196608) { s = w1; d = e1; off = i - 131072; }
    else if (i < 262144) { s = w2; d = e2; off = i - 196608; }
    else                 { s = w3; d = e3; off = i - 262144; }
    float4 v = reinterpret_cast<const float4*>(s)[off];
    v.x = expf(v.x); v.y = expf(v.y); v.z = expf(v.z); v.w = expf(v.w);
    reinterpret_cast<float4*>(d)[off] = v;
}

// ---------------------------------------------------------------------------
template <int N>
__device__ __forceinline__ void ld_vec(const float* __restrict__ p, float* r) {
    if constexpr (N == 4) {
        float4 v = *(const float4*)p;
        r[0] = v.x; r[1] = v.y; r[2] = v.z; r[3] = v.w;
    } else {
        float2 v = *(const float2*)p;
        r[0] = v.x; r[1] = v.y;
    }
}

// ---------------------------------------------------------------------------
// GEMM + log + bias:  C[m,n] = log( sum_k A[m,k]*Bw[n,k] ) + bias[n]
// 256 threads, BK=16, double-buffered smem, register prefetch.
// Thread grid: (BN/TN) x (BM/TM) must equal 256.
// ---------------------------------------------------------------------------
template <int BM, int BN, int TM, int TN>
__global__ __launch_bounds__(256) void gemm_log_k(
    const float* __restrict__ A, const float* __restrict__ Bw,
    const float* __restrict__ bias, float* __restrict__ C, int OUT) {
    constexpr int BK = 16;
    constexpr int NT = 256;
    constexpr int AF = BM * BK / NT;   // floats per thread, A tile
    constexpr int BF = BN * BK / NT;   // floats per thread, B tile
    constexpr int NX = BN / TN;        // threads along N

    __shared__ float As[2][BK][BM];
    __shared__ float Bs[2][BK][BN];

    const int tid = threadIdx.x;
    const int tx = tid % NX;
    const int ty = tid / NX;
    const int bm = blockIdx.y * BM;
    const int bn = blockIdx.x * BN;

    const int alr = tid % BM, alc = (tid / BM) * AF;
    const int blr = tid % BN, blc = (tid / BN) * BF;
    const float* Ap = A + (bm + alr) * KDIM + alc;
    const float* Bp = Bw + (bn + blr) * KDIM + blc;

    float acc[TM][TN] = {};
    float ar[AF], br[BF];

    // prologue: tile 0
    ld_vec<AF>(Ap, ar);
    ld_vec<BF>(Bp, br);
#pragma unroll
    for (int i = 0; i < AF; i++) As[0][alc + i][alr] = ar[i];
#pragma unroll
    for (int i = 0; i < BF; i++) Bs[0][blc + i][blr] = br[i];
    __syncthreads();

#pragma unroll 1
    for (int t = 0; t < KDIM / BK - 1; t++) {
        const int cur = t & 1, nxt = cur ^ 1;
        ld_vec<AF>(Ap + (t + 1) * BK, ar);
        ld_vec<BF>(Bp + (t + 1) * BK, br);

#pragma unroll
        for (int kk = 0; kk < BK; kk++) {
            float a[TM], b[TN];
#pragma unroll
            for (int i = 0; i < TM; i += (TM >= 4 ? 4 : TM))
                ld_vec<(TM >= 4 ? 4 : TM)>(&As[cur][kk][ty * TM + i], a + i);
            ld_vec<TN>(&Bs[cur][kk][tx * TN], b);
#pragma unroll
            for (int r = 0; r < TM; r++)
#pragma unroll
                for (int s = 0; s < TN; s++)
                    acc[r][s] = fmaf(a[r], b[s], acc[r][s]);
        }

#pragma unroll
        for (int i = 0; i < AF; i++) As[nxt][alc + i][alr] = ar[i];
#pragma unroll
        for (int i = 0; i < BF; i++) Bs[nxt][blc + i][blr] = br[i];
        __syncthreads();
    }

    {   // last tile
        const int cur = (KDIM / BK - 1) & 1;
#pragma unroll
        for (int kk = 0; kk < BK; kk++) {
            float a[TM], b[TN];
#pragma unroll
            for (int i = 0; i < TM; i += (TM >= 4 ? 4 : TM))
                ld_vec<(TM >= 4 ? 4 : TM)>(&As[cur][kk][ty * TM + i], a + i);
            ld_vec<TN>(&Bs[cur][kk][tx * TN], b);
#pragma unroll
            for (int r = 0; r < TM; r++)
#pragma unroll
                for (int s = 0; s < TN; s++)
                    acc[r][s] = fmaf(a[r], b[s], acc[r][s]);
        }
    }

    float bl[TN];
    ld_vec<TN>(bias + bn + tx * TN, bl);
#pragma unroll
    for (int r = 0; r < TM; r++) {
        float o[TN];
#pragma unroll
        for (int s = 0; s < TN; s++) o[s] = logf(acc[r][s]) + bl[s];
        float* Cp = C + (bm + ty * TM + r) * OUT + bn + tx * TN;
        if constexpr (TN == 4) *(float4*)Cp = make_float4(o[0], o[1], o[2], o[3]);
        else                   *(float2*)Cp = make_float2(o[0], o[1]);
    }
}

// ---------------------------------------------------------------------------
// trop_layernorm (median/IQR via hybrid bitonic sort) + relu + exp.
// 256 threads/row; j<=16 steps via shfl, j=256 in-thread, j in {32,64,128}
// via smem (9 barriered steps total).
// ---------------------------------------------------------------------------
__global__ __launch_bounds__(256) void ln_kernel(const float* __restrict__ H,
                                                 const float* __restrict__ w,
                                                 const float* __restrict__ b,
                                                 float* __restrict__ Exout) {
    __shared__ float s[512];
    const int row = blockIdx.x;
    const int t = threadIdx.x;
    const float* Hrow = H + row * 512;

    const float h0 = Hrow[t];
    const float h1 = Hrow[t + 256];
    float v0 = h0, v1 = h1;

#pragma unroll
    for (int k = 2; k <= 512; k <<= 1) {
        if (k == 512) {
            float m = fminf(v0, v1), M = fmaxf(v0, v1);
            v0 = m; v1 = M;
        }
#pragma unroll
        for (int j = (k >> 1) > 128 ? 128 : (k >> 1); j >= 32; j >>= 1) {
            __syncthreads();
            s[t] = v0; s[t + 256] = v1;
            __syncthreads();
            float p0 = s[t ^ j];
            float p1 = s[(t ^ j) + 256];
            bool asc0 = ((t & k) == 0);
            bool asc1 = (((t + 256) & k) == 0);
            bool low = ((t & j) == 0);
            v0 = (low == asc0) ? fminf(v0, p0) : fmaxf(v0, p0);
            v1 = (low == asc1) ? fminf(v1, p1) : fmaxf(v1, p1);
        }
#pragma unroll
        for (int j = (k >> 1) > 16 ? 16 : (k >> 1); j >= 1; j >>= 1) {
            bool asc0 = ((t & k) == 0);
            bool asc1 = (((t + 256) & k) == 0);
            bool low = ((t & j) == 0);
            float p0 = __shfl_xor_sync(0xffffffffu, v0, j);
            float p1 = __shfl_xor_sync(0xffffffffu, v1, j);
            v0 = (low == asc0) ? fminf(v0, p0) : fmaxf(v0, p0);
            v1 = (low == asc1) ? fminf(v1, p1) : fmaxf(v1, p1);
        }
    }

    __syncthreads();
    if (t == 127) { s[0] = v0; s[3] = v1; }
    if (t == 128) { s[1] = v0; s[4] = v1; }
    if (t == 255) { s[2] = v0; }
    __syncthreads();
    const float q25 = s[0] + 0.75f * (s[1] - s[0]);
    const float med = s[2];
    const float q75 = s[3] + 0.25f * (s[4] - s[3]);
    const float inv = 1.0f / fmaxf(q75 - q25, 1e-6f);

    float o0 = fmaxf((h0 - med) * inv * w[t] + b[t], 0.0f);
    float o1 = fmaxf((h1 - med) * inv * w[t + 256] + b[t + 256], 0.0f);
    Exout[row * 512 + t]       = expf(o0);
    Exout[row * 512 + t + 256] = expf(o1);
}

// ---------------------------------------------------------------------------
extern "C" void kernel_launch(void* const* d_in, const int* in_sizes, int n_in,
                              void* d_out, int out_size) {
    const float* x    = (const float*)d_in[0];
    const float* w1   = (const float*)d_in[1];
    const float* b1   = (const float*)d_in[2];
    const float* ln1w = (const float*)d_in[3];
    const float* ln1b = (const float*)d_in[4];
    const float* w2   = (const float*)d_in[5];
    const float* b2   = (const float*)d_in[6];
    const float* ln2w = (const float*)d_in[7];
    const float* ln2b = (const float*)d_in[8];
    const float* w3   = (const float*)d_in[9];
    const float* b3   = (const float*)d_in[10];

    float *Ew1, *Ew2, *Ew3, *bufA, *bufB, *H;
    cudaGetSymbolAddress((void**)&Ew1, g_Ew1);
    cudaGetSymbolAddress((void**)&Ew2, g_Ew2);
    cudaGetSymbolAddress((void**)&Ew3, g_Ew3);
    cudaGetSymbolAddress((void**)&bufA, g_bufA);
    cudaGetSymbolAddress((void**)&bufB, g_bufB);
    cudaGetSymbolAddress((void**)&H, g_H);

    exp_all_kernel<<<1152, 256>>>(x, bufA, w1, Ew1, w2, Ew2, w3, Ew3);

    dim3 g12(512 / 64, 1024 / 64);   // 8 x 16 = 128 CTAs
    dim3 g3(256 / 32, 1024 / 64);    // 8 x 16 = 128 CTAs

    gemm_log_k<64, 64, 4, 4><<<g12, 256>>>(bufA, Ew1, b1, H, 512);
    ln_kernel<<<1024, 256>>>(H, ln1w, ln1b, bufB);
    gemm_log_k<64, 64, 4, 4><<<g12, 256>>>(bufB, Ew2, b2, H, 512);
    ln_kernel<<<1024, 256>>>(H, ln2w, ln2b, bufA);
    gemm_log_k<64, 32, 4, 2><<<g3, 256>>>(bufA, Ew3, b3, (float*)d_out, 256);
}

// round 6
// speedup vs baseline: 1.2667x; 1.2667x over previous
#include <cuda_runtime.h>
#include <math.h>

// ---------------------------------------------------------------------------
// TropicalMLP: with temp=1, trop_linear(x;W,b) = log(exp(x) @ exp(W)^T) + b.
// fused exp -> GEMM+log -> sortLN+relu+exp -> GEMM+log -> sortLN+relu+exp
// -> GEMM+log.  GEMMs in fp32 FFMA (LN's tiny IQR amplifies rounding ~100x;
// tf32/bf16 unsafe at 1e-3).
// R4 change: BK=32 + explicit double-buffered fragment registers over kk
// (software pipeline the LDS->FFMA chain ptxas refused to pipeline at 47
// regs). Barriers per CTA: 32 -> 16.
// ---------------------------------------------------------------------------

#define KDIM 512

__device__ float g_Ew1[512 * 512];
__device__ float g_Ew2[512 * 512];
__device__ float g_Ew3[256 * 512];
__device__ float g_bufA[1024 * 512];
__device__ float g_bufB[1024 * 512];
__device__ float g_H[1024 * 512];

// ---------------------------------------------------------------------------
__global__ __launch_bounds__(256) void exp_all_kernel(
    const float* __restrict__ x,  float* __restrict__ ex,
    const float* __restrict__ w1, float* __restrict__ e1,
    const float* __restrict__ w2, float* __restrict__ e2,
    const float* __restrict__ w3, float* __restrict__ e3) {
    int i = blockIdx.x * 256 + threadIdx.x;  // float4 index
    const float* s; float* d; int off;
    if (i < 131072)      { s = x;  d = ex; off = i; }
    else if (i < 196608) { s = w1; d = e1; off = i - 131072; }
    else if (i < 262144) { s = w2; d = e2; off = i - 196608; }
    else                 { s = w3; d = e3; off = i - 262144; }
    float4 v = reinterpret_cast<const float4*>(s)[off];
    v.x = expf(v.x); v.y = expf(v.y); v.z = expf(v.z); v.w = expf(v.w);
    reinterpret_cast<float4*>(d)[off] = v;
}

// ---------------------------------------------------------------------------
template <int N>
__device__ __forceinline__ void ld_vec(const float* __restrict__ p, float* r) {
    if constexpr (N == 8) {
        float4 v = *(const float4*)p;
        float4 u = *(const float4*)(p + 4);
        r[0] = v.x; r[1] = v.y; r[2] = v.z; r[3] = v.w;
        r[4] = u.x; r[5] = u.y; r[6] = u.z; r[7] = u.w;
    } else if constexpr (N == 4) {
        float4 v = *(const float4*)p;
        r[0] = v.x; r[1] = v.y; r[2] = v.z; r[3] = v.w;
    } else {
        float2 v = *(const float2*)p;
        r[0] = v.x; r[1] = v.y;
    }
}

// ---------------------------------------------------------------------------
// GEMM + log + bias:  C[m,n] = log( sum_k A[m,k]*Bw[n,k] ) + bias[n]
// 256 threads, BK=32, double-buffered smem + double-buffered kk fragments.
// ---------------------------------------------------------------------------
template <int BM, int BN, int TM, int TN>
__global__ __launch_bounds__(256) void gemm_log_k(
    const float* __restrict__ A, const float* __restrict__ Bw,
    const float* __restrict__ bias, float* __restrict__ C, int OUT) {
    constexpr int BK = 32;
    constexpr int NT = 256;
    constexpr int AF = BM * BK / NT;   // floats per thread, A tile (8)
    constexpr int BF = BN * BK / NT;   // floats per thread, B tile (8 or 4)
    constexpr int NX = BN / TN;        // threads along N
    constexpr int NTILE = KDIM / BK;   // 16

    __shared__ float As[2][BK][BM];
    __shared__ float Bs[2][BK][BN];

    const int tid = threadIdx.x;
    const int tx = tid % NX;
    const int ty = tid / NX;
    const int bm = blockIdx.y * BM;
    const int bn = blockIdx.x * BN;

    const int alr = tid % BM, alc = (tid / BM) * AF;
    const int blr = tid % BN, blc = (tid / BN) * BF;
    const float* Ap = A + (bm + alr) * KDIM + alc;
    const float* Bp = Bw + (bn + blr) * KDIM + blc;

    float acc[TM][TN] = {};
    float ar[AF], br[BF];
    float af[2][TM], bf[2][TN];

    // prologue: stage tile 0 through registers into smem buffer 0
    ld_vec<AF>(Ap, ar);
    ld_vec<BF>(Bp, br);
#pragma unroll
    for (int i = 0; i < AF; i++) As[0][alc + i][alr] = ar[i];
#pragma unroll
    for (int i = 0; i < BF; i++) Bs[0][blc + i][blr] = br[i];
    __syncthreads();

#pragma unroll 1
    for (int t = 0; t < NTILE; t++) {
        const int cur = t & 1, nxt = cur ^ 1;
        const bool more = (t + 1 < NTILE);

        if (more) {  // global prefetch of next k-tile
            ld_vec<AF>(Ap + (t + 1) * BK, ar);
            ld_vec<BF>(Bp + (t + 1) * BK, br);
        }

        // kk-pipelined compute: load frag kk+1 while FMA'ing frag kk
        ld_vec<TM>(&As[cur][0][ty * TM], af[0]);
        ld_vec<TN>(&Bs[cur][0][tx * TN], bf[0]);
#pragma unroll
        for (int kk = 0; kk < BK; kk++) {
            const int c = kk & 1, n = c ^ 1;
            if (kk + 1 < BK) {
                ld_vec<TM>(&As[cur][kk + 1][ty * TM], af[n]);
                ld_vec<TN>(&Bs[cur][kk + 1][tx * TN], bf[n]);
            }
#pragma unroll
            for (int r = 0; r < TM; r++)
#pragma unroll
                for (int s = 0; s < TN; s++)
                    acc[r][s] = fmaf(af[c][r], bf[c][s], acc[r][s]);
        }

        if (more) {
#pragma unroll
            for (int i = 0; i < AF; i++) As[nxt][alc + i][alr] = ar[i];
#pragma unroll
            for (int i = 0; i < BF; i++) Bs[nxt][blc + i][blr] = br[i];
            __syncthreads();
        }
    }

    // epilogue: log + bias
    float bl[TN];
    ld_vec<TN>(bias + bn + tx * TN, bl);
#pragma unroll
    for (int r = 0; r < TM; r++) {
        float o[TN];
#pragma unroll
        for (int s = 0; s < TN; s++) o[s] = logf(acc[r][s]) + bl[s];
        float* Cp = C + (bm + ty * TM + r) * OUT + bn + tx * TN;
        if constexpr (TN == 4) *(float4*)Cp = make_float4(o[0], o[1], o[2], o[3]);
        else                   *(float2*)Cp = make_float2(o[0], o[1]);
    }
}

// ---------------------------------------------------------------------------
// trop_layernorm (median/IQR via hybrid bitonic sort) + relu + exp.
// 256 threads/row; j<=16 steps via shfl, j=256 in-thread, j in {32,64,128}
// via smem (9 barriered steps total).
// ---------------------------------------------------------------------------
__global__ __launch_bounds__(256) void ln_kernel(const float* __restrict__ H,
                                                 const float* __restrict__ w,
                                                 const float* __restrict__ b,
                                                 float* __restrict__ Exout) {
    __shared__ float s[512];
    const int row = blockIdx.x;
    const int t = threadIdx.x;
    const float* Hrow = H + row * 512;

    const float h0 = Hrow[t];
    const float h1 = Hrow[t + 256];
    float v0 = h0, v1 = h1;

#pragma unroll
    for (int k = 2; k <= 512; k <<= 1) {
        if (k == 512) {
            float m = fminf(v0, v1), M = fmaxf(v0, v1);
            v0 = m; v1 = M;
        }
#pragma unroll
        for (int j = (k >> 1) > 128 ? 128 : (k >> 1); j >= 32; j >>= 1) {
            __syncthreads();
            s[t] = v0; s[t + 256] = v1;
            __syncthreads();
            float p0 = s[t ^ j];
            float p1 = s[(t ^ j) + 256];
            bool asc0 = ((t & k) == 0);
            bool asc1 = (((t + 256) & k) == 0);
            bool low = ((t & j) == 0);
            v0 = (low == asc0) ? fminf(v0, p0) : fmaxf(v0, p0);
            v1 = (low == asc1) ? fminf(v1, p1) : fmaxf(v1, p1);
        }
#pragma unroll
        for (int j = (k >> 1) > 16 ? 16 : (k >> 1); j >= 1; j >>= 1) {
            bool asc0 = ((t & k) == 0);
            bool asc1 = (((t + 256) & k) == 0);
            bool low = ((t & j) == 0);
            float p0 = __shfl_xor_sync(0xffffffffu, v0, j);
            float p1 = __shfl_xor_sync(0xffffffffu, v1, j);
            v0 = (low == asc0) ? fminf(v0, p0) : fmaxf(v0, p0);
            v1 = (low == asc1) ? fminf(v1, p1) : fmaxf(v1, p1);
        }
    }

    __syncthreads();
    if (t == 127) { s[0] = v0; s[3] = v1; }
    if (t == 128) { s[1] = v0; s[4] = v1; }
    if (t == 255) { s[2] = v0; }
    __syncthreads();
    const float q25 = s[0] + 0.75f * (s[1] - s[0]);
    const float med = s[2];
    const float q75 = s[3] + 0.25f * (s[4] - s[3]);
    const float inv = 1.0f / fmaxf(q75 - q25, 1e-6f);

    float o0 = fmaxf((h0 - med) * inv * w[t] + b[t], 0.0f);
    float o1 = fmaxf((h1 - med) * inv * w[t + 256] + b[t + 256], 0.0f);
    Exout[row * 512 + t]       = expf(o0);
    Exout[row * 512 + t + 256] = expf(o1);
}

// ---------------------------------------------------------------------------
extern "C" void kernel_launch(void* const* d_in, const int* in_sizes, int n_in,
                              void* d_out, int out_size) {
    const float* x    = (const float*)d_in[0];
    const float* w1   = (const float*)d_in[1];
    const float* b1   = (const float*)d_in[2];
    const float* ln1w = (const float*)d_in[3];
    const float* ln1b = (const float*)d_in[4];
    const float* w2   = (const float*)d_in[5];
    const float* b2   = (const float*)d_in[6];
    const float* ln2w = (const float*)d_in[7];
    const float* ln2b = (const float*)d_in[8];
    const float* w3   = (const float*)d_in[9];
    const float* b3   = (const float*)d_in[10];

    float *Ew1, *Ew2, *Ew3, *bufA, *bufB, *H;
    cudaGetSymbolAddress((void**)&Ew1, g_Ew1);
    cudaGetSymbolAddress((void**)&Ew2, g_Ew2);
    cudaGetSymbolAddress((void**)&Ew3, g_Ew3);
    cudaGetSymbolAddress((void**)&bufA, g_bufA);
    cudaGetSymbolAddress((void**)&bufB, g_bufB);
    cudaGetSymbolAddress((void**)&H, g_H);

    exp_all_kernel<<<1152, 256>>>(x, bufA, w1, Ew1, w2, Ew2, w3, Ew3);

    dim3 g12(512 / 64, 1024 / 64);   // 8 x 16 = 128 CTAs
    dim3 g3(256 / 32, 1024 / 64);    // 8 x 16 = 128 CTAs

    gemm_log_k<64, 64, 4, 4><<<g12, 256>>>(bufA, Ew1, b1, H, 512);
    ln_kernel<<<1024, 256>>>(H, ln1w, ln1b, bufB);
    gemm_log_k<64, 64, 4, 4><<<g12, 256>>>(bufB, Ew2, b2, H, 512);
    ln_kernel<<<1024, 256>>>(H, ln2w, ln2b, bufA);
    gemm_log_k<64, 32, 4, 2><<<g3, 256>>>(bufA, Ew3, b3, (float*)d_out, 256);
}